// round 14
// baseline (speedup 1.0000x reference)
#include <cuda_runtime.h>
#include <cuda_bf16.h>
#include <cstddef>

// ---------------------------------------------------------------------------
// Model_53901839564895: CNN forward
//   conv1 5x5 pad1 (3->5) -> relu -> BN(eval) -> maxpool 3,2,1   -> [512,5,63,63]
//   conv2 3x3 pad1 (5->9) -> relu -> maxpool 3,2,1               -> (fused out)
//   conv3 3x3 pad1 (9->16) -> flatten -> FC(16384->6) -> softmax
// conv3+FC folded into W_eff (R12); GEMV fused into K2 (R13).
// R14: K2 two-pass channel halo (smem 35.3->29.9KB) -> 7 CTAs/SM.
// Weight layout quirk: effective conv weight = raw buffer indexed as
//   w[((c*KH+ki)*KW+kj)*COUT + o]
// ---------------------------------------------------------------------------

#define BATCH 512

// Static scratch
__device__ float g_p1[(size_t)BATCH * 5 * 63 * 63];
__device__ float g_weff[6 * 9216];              // folded conv3+FC weights
__device__ float g_part[(size_t)BATCH * 8 * 6]; // per-K2-block partial logits

// ===========================================================================
// K1: conv1+relu+BN+maxpool. UNCHANGED (216us, ~90% of issue floor).
// ===========================================================================
__global__ __launch_bounds__(192, 7) void k1_conv_bn_pool(
    const float* __restrict__ x, const float* __restrict__ k1,
    const float* __restrict__ gamma, const float* __restrict__ beta)
{
    __shared__ float sw[375];
    __shared__ float sscale[5], sbeta[5];
    __shared__ float sin[3][21][37];
    __shared__ float sconv[5][17][33];

    const int tid = threadIdx.x;
    const int b   = blockIdx.z;
    const int px0 = blockIdx.x * 16;
    const int py0 = blockIdx.y * 8;
    const int cy0 = 2 * py0 - 1;
    const int cx0 = 2 * px0 - 1;

    for (int i = tid; i < 375; i += 192) sw[i] = k1[i];
    if (tid < 5) {
        sscale[tid] = gamma[tid] * rsqrtf(1.0f + 1e-5f);
        sbeta[tid]  = beta[tid];
    }

    const float* xb = x + (size_t)b * 3 * 128 * 128;
    if (tid < 185) {
        const int tj = tid % 37;
        const int rg = tid / 37;
        const int ix = cx0 - 1 + tj;
        const bool xok = (ix >= 0 && ix < 128);
        #pragma unroll 1
        for (int row = rg; row < 63; row += 5) {
            int c  = (row >= 21) + (row >= 42);
            int li = row - c * 21;
            int iy = cy0 - 1 + li;
            float v = 0.0f;
            if (xok && iy >= 0 && iy < 128)
                v = xb[(c * 128 + iy) * 128 + ix];
            sin[c][li][tj] = v;
        }
    }
    __syncthreads();

    if (tid < 187) {
        const int y  = tid / 11;
        const int x0 = (tid % 11) * 3;

        float acc[3][5];
        #pragma unroll
        for (int xi = 0; xi < 3; xi++)
            #pragma unroll
            for (int o = 0; o < 5; o++) acc[xi][o] = 0.0f;

        #pragma unroll
        for (int c = 0; c < 3; c++) {
            #pragma unroll
            for (int ki = 0; ki < 5; ki++) {
                float r[7];
                #pragma unroll
                for (int j = 0; j < 7; j++) r[j] = sin[c][y + ki][x0 + j];
                #pragma unroll
                for (int kj = 0; kj < 5; kj++) {
                    const float* wp = &sw[((c * 5 + ki) * 5 + kj) * 5];
                    #pragma unroll
                    for (int o = 0; o < 5; o++) {
                        float wv = wp[o];
                        acc[0][o] = fmaf(r[kj],     wv, acc[0][o]);
                        acc[1][o] = fmaf(r[kj + 1], wv, acc[1][o]);
                        acc[2][o] = fmaf(r[kj + 2], wv, acc[2][o]);
                    }
                }
            }
        }
        const int cy = cy0 + y;
        const bool yok = (cy >= 0 && cy < 126);
        #pragma unroll
        for (int xi = 0; xi < 3; xi++) {
            int cx = cx0 + x0 + xi;
            bool ok = yok && (cx >= 0) && (cx < 126);
            #pragma unroll
            for (int o = 0; o < 5; o++) {
                float v = 0.0f;
                if (ok) v = fmaf(fmaxf(acc[xi][o], 0.0f), sscale[o], sbeta[o]);
                sconv[o][y][x0 + xi] = v;
            }
        }
    }
    __syncthreads();

    float* p1b = g_p1 + (size_t)b * 5 * 63 * 63;
    for (int idx = tid; idx < 5 * 128; idx += 192) {
        int o = idx >> 7, rem = idx & 127;
        int ly = rem >> 4, lx = rem & 15;
        int py = py0 + ly, px = px0 + lx;
        if (py < 63 && px < 63) {
            float m = -1e30f;
            #pragma unroll
            for (int dy = 0; dy < 3; dy++)
                #pragma unroll
                for (int dx = 0; dx < 3; dx++)
                    m = fmaxf(m, sconv[o][2 * ly + dy][2 * lx + dx]);
            p1b[(o * 63 + py) * 63 + px] = m;
        }
    }
}

// ===========================================================================
// K3a: fold conv3 into FC (unchanged). Runs before K2.
// ===========================================================================
__global__ __launch_bounds__(256) void k3a_fold(
    const float* __restrict__ k3, const float* __restrict__ fc_w)
{
    __shared__ float sk[1296];
    const int tid = threadIdx.x;
    for (int i = tid; i < 1296; i += 256) sk[i] = k3[i];
    __syncthreads();

    int idx = blockIdx.x * 256 + tid;
    if (idx >= 6 * 9216) return;
    const int j   = idx / 9216;
    const int rem = idx % 9216;
    const int c   = rem >> 10;
    const int iy  = (rem & 1023) >> 5;
    const int ix  = rem & 31;

    const float* wj = fc_w + (size_t)j * 16384;
    float s = 0.0f;
    #pragma unroll
    for (int ki = 0; ki < 3; ki++) {
        int y = iy + 1 - ki;
        if (y < 0 || y >= 32) continue;
        #pragma unroll
        for (int kj = 0; kj < 3; kj++) {
            int xx = ix + 1 - kj;
            if (xx < 0 || xx >= 32) continue;
            const float* kp = &sk[((c * 3 + ki) * 3 + kj) * 16];
            const float* fp = wj + y * 32 + xx;
            #pragma unroll
            for (int o = 0; o < 16; o++)
                s = fmaf(kp[o], fp[o * 1024], s);
        }
    }
    g_weff[idx] = s;
}

// ===========================================================================
// K2: conv2+relu+maxpool fused with W_eff dot. R14: TWO-PASS channel halo —
// sin3 holds 3 channels (8KB instead of 13.3KB); conv accumulates c=0..2,
// reloads c=3..4 into the same buffer, finishes. smem 29.9KB -> 7 CTAs/SM.
// grid (2,4,512), blk id = by*2+bx.
// ===========================================================================
__global__ __launch_bounds__(192, 7) void k2_conv_pool_dot(const float* __restrict__ k2)
{
    __shared__ float sw[405];
    __shared__ float sin3[3][19][35];    // channel-chunk halo buffer
    __shared__ float sconv[9][17][33];
    __shared__ float sred[6][6];         // [warp][logit]

    const int tid = threadIdx.x;
    const int b   = blockIdx.z;
    const int px0 = blockIdx.x * 16;
    const int py0 = blockIdx.y * 8;
    const int cy0 = 2 * py0 - 1;
    const int cx0 = 2 * px0 - 1;

    for (int i = tid; i < 405; i += 192) sw[i] = k2[i];

    const float* pin = g_p1 + (size_t)b * 5 * 63 * 63;
    const int tj = tid % 35;
    const int rg = tid / 35;
    const int ix = cx0 - 1 + tj;
    const bool xok = (ix >= 0 && ix < 63);

    // Pass A halo: channels 0..2 (57 rows of 35)
    if (tid < 175) {
        #pragma unroll 1
        for (int row = rg; row < 57; row += 5) {
            int c  = (row >= 19) + (row >= 38);
            int li = row - c * 19;
            int iy = cy0 - 1 + li;
            float v = 0.0f;
            if (xok && iy >= 0 && iy < 63)
                v = pin[(c * 63 + iy) * 63 + ix];
            sin3[c][li][tj] = v;
        }
    }
    __syncthreads();

    const int y  = tid / 11;             // valid for tid<187
    const int x0 = (tid % 11) * 3;

    float acc[3][9];
    #pragma unroll
    for (int xi = 0; xi < 3; xi++)
        #pragma unroll
        for (int o = 0; o < 9; o++) acc[xi][o] = 0.0f;

    // Pass A conv: c = 0..2
    if (tid < 187) {
        #pragma unroll
        for (int c = 0; c < 3; c++) {
            #pragma unroll
            for (int ki = 0; ki < 3; ki++) {
                float r[5];
                #pragma unroll
                for (int j = 0; j < 5; j++) r[j] = sin3[c][y + ki][x0 + j];
                #pragma unroll
                for (int kj = 0; kj < 3; kj++) {
                    const float* wp = &sw[((c * 3 + ki) * 3 + kj) * 9];
                    #pragma unroll
                    for (int o = 0; o < 9; o++) {
                        float wv = wp[o];
                        acc[0][o] = fmaf(r[kj],     wv, acc[0][o]);
                        acc[1][o] = fmaf(r[kj + 1], wv, acc[1][o]);
                        acc[2][o] = fmaf(r[kj + 2], wv, acc[2][o]);
                    }
                }
            }
        }
    }
    __syncthreads();                     // sin3 fully consumed

    // Pass B halo: channels 3..4 into sin3[0..1] (38 rows)
    if (tid < 175) {
        #pragma unroll 1
        for (int row = rg; row < 38; row += 5) {
            int c2 = (row >= 19);
            int li = row - c2 * 19;
            int iy = cy0 - 1 + li;
            float v = 0.0f;
            if (xok && iy >= 0 && iy < 63)
                v = pin[((3 + c2) * 63 + iy) * 63 + ix];
            sin3[c2][li][tj] = v;
        }
    }
    __syncthreads();

    // Pass B conv: c = 3..4 (buffer slots 0..1), then relu + sconv writeback
    if (tid < 187) {
        #pragma unroll
        for (int c2 = 0; c2 < 2; c2++) {
            const int c = 3 + c2;
            #pragma unroll
            for (int ki = 0; ki < 3; ki++) {
                float r[5];
                #pragma unroll
                for (int j = 0; j < 5; j++) r[j] = sin3[c2][y + ki][x0 + j];
                #pragma unroll
                for (int kj = 0; kj < 3; kj++) {
                    const float* wp = &sw[((c * 3 + ki) * 3 + kj) * 9];
                    #pragma unroll
                    for (int o = 0; o < 9; o++) {
                        float wv = wp[o];
                        acc[0][o] = fmaf(r[kj],     wv, acc[0][o]);
                        acc[1][o] = fmaf(r[kj + 1], wv, acc[1][o]);
                        acc[2][o] = fmaf(r[kj + 2], wv, acc[2][o]);
                    }
                }
            }
        }
        const int cy = cy0 + y;
        const bool yok = (cy >= 0 && cy < 63);
        #pragma unroll
        for (int xi = 0; xi < 3; xi++) {
            int cx = cx0 + x0 + xi;
            bool ok = yok && (cx >= 0) && (cx < 63);
            #pragma unroll
            for (int o = 0; o < 9; o++) {
                float v = 0.0f;
                if (ok) v = fmaxf(acc[xi][o], 0.0f);
                sconv[o][y][x0 + xi] = v;
            }
        }
    }
    __syncthreads();

    // Pool + dot with W_eff (flat f = o*1024 + py*32 + px), 6 iters/thread
    float part[6];
    #pragma unroll
    for (int j = 0; j < 6; j++) part[j] = 0.0f;

    for (int idx = tid; idx < 9 * 128; idx += 192) {
        int o = idx >> 7, rem = idx & 127;
        int ly = rem >> 4, lx = rem & 15;
        int py = py0 + ly, px = px0 + lx;   // always < 32
        float m = -1e30f;
        #pragma unroll
        for (int dy = 0; dy < 3; dy++)
            #pragma unroll
            for (int dx = 0; dx < 3; dx++)
                m = fmaxf(m, sconv[o][2 * ly + dy][2 * lx + dx]);
        const int f = o * 1024 + py * 32 + px;
        #pragma unroll
        for (int j = 0; j < 6; j++)
            part[j] = fmaf(m, g_weff[j * 9216 + f], part[j]);
    }

    // Block reduce: 6 warps -> sred -> thread j sums column j
    #pragma unroll
    for (int j = 0; j < 6; j++) {
        float v = part[j];
        #pragma unroll
        for (int off = 16; off > 0; off >>= 1)
            v += __shfl_down_sync(0xffffffffu, v, off);
        if ((tid & 31) == 0) sred[tid >> 5][j] = v;
    }
    __syncthreads();
    if (tid < 6) {
        float s = 0.0f;
        #pragma unroll
        for (int w = 0; w < 6; w++) s += sred[w][tid];
        const int blk = blockIdx.y * 2 + blockIdx.x;   // 0..7
        g_part[((size_t)b * 8 + blk) * 6 + tid] = s;
    }
}

// ===========================================================================
// K3c: reduce 8 block-partials per image + bias, softmax.
// ===========================================================================
__global__ __launch_bounds__(256) void k3c_softmax(
    const float* __restrict__ fc_b, float* __restrict__ out)
{
    const int i = blockIdx.x * 256 + threadIdx.x;
    if (i >= BATCH) return;
    const float* pp = g_part + (size_t)i * 48;
    float lg[6];
    #pragma unroll
    for (int j = 0; j < 6; j++) lg[j] = fc_b[j];
    #pragma unroll
    for (int blk = 0; blk < 8; blk++)
        #pragma unroll
        for (int j = 0; j < 6; j++) lg[j] += pp[blk * 6 + j];

    float mx = lg[0];
    #pragma unroll
    for (int j = 1; j < 6; j++) mx = fmaxf(mx, lg[j]);
    float e[6], s = 0.0f;
    #pragma unroll
    for (int j = 0; j < 6; j++) { e[j] = expf(lg[j] - mx); s += e[j]; }
    float inv = 1.0f / s;
    #pragma unroll
    for (int j = 0; j < 6; j++) out[i * 6 + j] = e[j] * inv;
}

// ===========================================================================
extern "C" void kernel_launch(void* const* d_in, const int* in_sizes, int n_in,
                              void* d_out, int out_size)
{
    const float* x     = (const float*)d_in[0];
    const float* k1    = (const float*)d_in[1];
    const float* gamma = (const float*)d_in[2];
    const float* beta  = (const float*)d_in[3];
    const float* k2    = (const float*)d_in[4];
    const float* k3    = (const float*)d_in[5];
    const float* fc_w  = (const float*)d_in[6];
    const float* fc_b  = (const float*)d_in[7];
    float* out = (float*)d_out;

    k1_conv_bn_pool<<<dim3(4, 8, BATCH), 192>>>(x, k1, gamma, beta);
    k3a_fold<<<216, 256>>>(k3, fc_w);          // W_eff ready before K2 (stream order)
    k2_conv_pool_dot<<<dim3(2, 4, BATCH), 192>>>(k2);
    k3c_softmax<<<2, 256>>>(fc_b, out);
}

// round 15
// speedup vs baseline: 1.0027x; 1.0027x over previous
#include <cuda_runtime.h>
#include <cuda_bf16.h>
#include <cstddef>

// ---------------------------------------------------------------------------
// Model_53901839564895: CNN forward
//   conv1 5x5 pad1 (3->5) -> relu -> BN(eval) -> maxpool 3,2,1   -> [512,5,63,63]
//   conv2 3x3 pad1 (5->9) -> relu -> maxpool 3,2,1               -> (fused out)
//   conv3 3x3 pad1 (9->16) -> flatten -> FC(16384->6) -> softmax
// conv3+FC folded into W_eff (R12); GEMV fused into K2 (R13).
// R15: softmax fused into last-arriving K2 block (threadfence-reduction
// pattern, self-resetting counter) -> k3c deleted. K1 -> (192,8).
// Weight layout quirk: effective conv weight = raw buffer indexed as
//   w[((c*KH+ki)*KW+kj)*COUT + o]
// ---------------------------------------------------------------------------

#define BATCH 512

// Static scratch
__device__ float g_p1[(size_t)BATCH * 5 * 63 * 63];
__device__ float g_weff[6 * 9216];              // folded conv3+FC weights
__device__ float g_part[(size_t)BATCH * 8 * 6]; // per-K2-block partial logits
__device__ int   g_cnt[BATCH];                  // zero-init; self-resetting

// ===========================================================================
// K1: conv1+relu+BN+maxpool. Code unchanged; bounds (192,8) — regs already 40,
// so the 8th CTA fits regs (61.4k) and smem (176KB).
// ===========================================================================
__global__ __launch_bounds__(192, 8) void k1_conv_bn_pool(
    const float* __restrict__ x, const float* __restrict__ k1,
    const float* __restrict__ gamma, const float* __restrict__ beta)
{
    __shared__ float sw[375];
    __shared__ float sscale[5], sbeta[5];
    __shared__ float sin[3][21][37];
    __shared__ float sconv[5][17][33];

    const int tid = threadIdx.x;
    const int b   = blockIdx.z;
    const int px0 = blockIdx.x * 16;
    const int py0 = blockIdx.y * 8;
    const int cy0 = 2 * py0 - 1;
    const int cx0 = 2 * px0 - 1;

    for (int i = tid; i < 375; i += 192) sw[i] = k1[i];
    if (tid < 5) {
        sscale[tid] = gamma[tid] * rsqrtf(1.0f + 1e-5f);
        sbeta[tid]  = beta[tid];
    }

    const float* xb = x + (size_t)b * 3 * 128 * 128;
    if (tid < 185) {
        const int tj = tid % 37;
        const int rg = tid / 37;
        const int ix = cx0 - 1 + tj;
        const bool xok = (ix >= 0 && ix < 128);
        #pragma unroll 1
        for (int row = rg; row < 63; row += 5) {
            int c  = (row >= 21) + (row >= 42);
            int li = row - c * 21;
            int iy = cy0 - 1 + li;
            float v = 0.0f;
            if (xok && iy >= 0 && iy < 128)
                v = xb[(c * 128 + iy) * 128 + ix];
            sin[c][li][tj] = v;
        }
    }
    __syncthreads();

    if (tid < 187) {
        const int y  = tid / 11;
        const int x0 = (tid % 11) * 3;

        float acc[3][5];
        #pragma unroll
        for (int xi = 0; xi < 3; xi++)
            #pragma unroll
            for (int o = 0; o < 5; o++) acc[xi][o] = 0.0f;

        #pragma unroll
        for (int c = 0; c < 3; c++) {
            #pragma unroll
            for (int ki = 0; ki < 5; ki++) {
                float r[7];
                #pragma unroll
                for (int j = 0; j < 7; j++) r[j] = sin[c][y + ki][x0 + j];
                #pragma unroll
                for (int kj = 0; kj < 5; kj++) {
                    const float* wp = &sw[((c * 5 + ki) * 5 + kj) * 5];
                    #pragma unroll
                    for (int o = 0; o < 5; o++) {
                        float wv = wp[o];
                        acc[0][o] = fmaf(r[kj],     wv, acc[0][o]);
                        acc[1][o] = fmaf(r[kj + 1], wv, acc[1][o]);
                        acc[2][o] = fmaf(r[kj + 2], wv, acc[2][o]);
                    }
                }
            }
        }
        const int cy = cy0 + y;
        const bool yok = (cy >= 0 && cy < 126);
        #pragma unroll
        for (int xi = 0; xi < 3; xi++) {
            int cx = cx0 + x0 + xi;
            bool ok = yok && (cx >= 0) && (cx < 126);
            #pragma unroll
            for (int o = 0; o < 5; o++) {
                float v = 0.0f;
                if (ok) v = fmaf(fmaxf(acc[xi][o], 0.0f), sscale[o], sbeta[o]);
                sconv[o][y][x0 + xi] = v;
            }
        }
    }
    __syncthreads();

    float* p1b = g_p1 + (size_t)b * 5 * 63 * 63;
    for (int idx = tid; idx < 5 * 128; idx += 192) {
        int o = idx >> 7, rem = idx & 127;
        int ly = rem >> 4, lx = rem & 15;
        int py = py0 + ly, px = px0 + lx;
        if (py < 63 && px < 63) {
            float m = -1e30f;
            #pragma unroll
            for (int dy = 0; dy < 3; dy++)
                #pragma unroll
                for (int dx = 0; dx < 3; dx++)
                    m = fmaxf(m, sconv[o][2 * ly + dy][2 * lx + dx]);
            p1b[(o * 63 + py) * 63 + px] = m;
        }
    }
}

// ===========================================================================
// K3a: fold conv3 into FC (unchanged). Runs before K2.
// ===========================================================================
__global__ __launch_bounds__(256) void k3a_fold(
    const float* __restrict__ k3, const float* __restrict__ fc_w)
{
    __shared__ float sk[1296];
    const int tid = threadIdx.x;
    for (int i = tid; i < 1296; i += 256) sk[i] = k3[i];
    __syncthreads();

    int idx = blockIdx.x * 256 + tid;
    if (idx >= 6 * 9216) return;
    const int j   = idx / 9216;
    const int rem = idx % 9216;
    const int c   = rem >> 10;
    const int iy  = (rem & 1023) >> 5;
    const int ix  = rem & 31;

    const float* wj = fc_w + (size_t)j * 16384;
    float s = 0.0f;
    #pragma unroll
    for (int ki = 0; ki < 3; ki++) {
        int y = iy + 1 - ki;
        if (y < 0 || y >= 32) continue;
        #pragma unroll
        for (int kj = 0; kj < 3; kj++) {
            int xx = ix + 1 - kj;
            if (xx < 0 || xx >= 32) continue;
            const float* kp = &sk[((c * 3 + ki) * 3 + kj) * 16];
            const float* fp = wj + y * 32 + xx;
            #pragma unroll
            for (int o = 0; o < 16; o++)
                s = fmaf(kp[o], fp[o * 1024], s);
        }
    }
    g_weff[idx] = s;
}

// ===========================================================================
// K2: conv2+relu+maxpool fused with W_eff dot (R13 single-pass version).
// R15: the LAST of the 8 blocks per image (threadfence-reduction pattern)
// also sums the 8 partials + bias and writes the softmax. grid (2,4,512).
// ===========================================================================
__global__ __launch_bounds__(192, 6) void k2_conv_pool_dot(
    const float* __restrict__ k2, const float* __restrict__ fc_b,
    float* __restrict__ out)
{
    __shared__ float sw[405];
    __shared__ float sin[5][19][35];
    __shared__ float sconv[9][17][33];
    __shared__ float sred[6][6];         // [warp][logit]

    const int tid = threadIdx.x;
    const int b   = blockIdx.z;
    const int px0 = blockIdx.x * 16;
    const int py0 = blockIdx.y * 8;
    const int cy0 = 2 * py0 - 1;
    const int cx0 = 2 * px0 - 1;

    for (int i = tid; i < 405; i += 192) sw[i] = k2[i];

    const float* pin = g_p1 + (size_t)b * 5 * 63 * 63;
    if (tid < 175) {
        const int tj = tid % 35;
        const int rg = tid / 35;
        const int ix = cx0 - 1 + tj;
        const bool xok = (ix >= 0 && ix < 63);
        #pragma unroll 1
        for (int row = rg; row < 95; row += 5) {
            int c  = (row >= 19) + (row >= 38) + (row >= 57) + (row >= 76);
            int li = row - c * 19;
            int iy = cy0 - 1 + li;
            float v = 0.0f;
            if (xok && iy >= 0 && iy < 63)
                v = pin[(c * 63 + iy) * 63 + ix];
            sin[c][li][tj] = v;
        }
    }
    __syncthreads();

    if (tid < 187) {
        const int y  = tid / 11;
        const int x0 = (tid % 11) * 3;

        float acc[3][9];
        #pragma unroll
        for (int xi = 0; xi < 3; xi++)
            #pragma unroll
            for (int o = 0; o < 9; o++) acc[xi][o] = 0.0f;

        #pragma unroll
        for (int c = 0; c < 5; c++) {
            #pragma unroll
            for (int ki = 0; ki < 3; ki++) {
                float r[5];
                #pragma unroll
                for (int j = 0; j < 5; j++) r[j] = sin[c][y + ki][x0 + j];
                #pragma unroll
                for (int kj = 0; kj < 3; kj++) {
                    const float* wp = &sw[((c * 3 + ki) * 3 + kj) * 9];
                    #pragma unroll
                    for (int o = 0; o < 9; o++) {
                        float wv = wp[o];
                        acc[0][o] = fmaf(r[kj],     wv, acc[0][o]);
                        acc[1][o] = fmaf(r[kj + 1], wv, acc[1][o]);
                        acc[2][o] = fmaf(r[kj + 2], wv, acc[2][o]);
                    }
                }
            }
        }
        const int cy = cy0 + y;
        const bool yok = (cy >= 0 && cy < 63);
        #pragma unroll
        for (int xi = 0; xi < 3; xi++) {
            int cx = cx0 + x0 + xi;
            bool ok = yok && (cx >= 0) && (cx < 63);
            #pragma unroll
            for (int o = 0; o < 9; o++) {
                float v = 0.0f;
                if (ok) v = fmaxf(acc[xi][o], 0.0f);
                sconv[o][y][x0 + xi] = v;
            }
        }
    }
    __syncthreads();

    // Pool + dot with W_eff (flat f = o*1024 + py*32 + px), 6 iters/thread
    float part[6];
    #pragma unroll
    for (int j = 0; j < 6; j++) part[j] = 0.0f;

    for (int idx = tid; idx < 9 * 128; idx += 192) {
        int o = idx >> 7, rem = idx & 127;
        int ly = rem >> 4, lx = rem & 15;
        int py = py0 + ly, px = px0 + lx;   // always < 32
        float m = -1e30f;
        #pragma unroll
        for (int dy = 0; dy < 3; dy++)
            #pragma unroll
            for (int dx = 0; dx < 3; dx++)
                m = fmaxf(m, sconv[o][2 * ly + dy][2 * lx + dx]);
        const int f = o * 1024 + py * 32 + px;
        #pragma unroll
        for (int j = 0; j < 6; j++)
            part[j] = fmaf(m, g_weff[j * 9216 + f], part[j]);
    }

    // Block reduce: 6 warps -> sred -> thread j writes partial logit j
    #pragma unroll
    for (int j = 0; j < 6; j++) {
        float v = part[j];
        #pragma unroll
        for (int off = 16; off > 0; off >>= 1)
            v += __shfl_down_sync(0xffffffffu, v, off);
        if ((tid & 31) == 0) sred[tid >> 5][j] = v;
    }
    __syncthreads();
    if (tid < 6) {
        float s = 0.0f;
        #pragma unroll
        for (int w = 0; w < 6; w++) s += sred[w][tid];
        const int blk = blockIdx.y * 2 + blockIdx.x;   // 0..7
        g_part[((size_t)b * 8 + blk) * 6 + tid] = s;
    }
    __syncthreads();

    // Last-block softmax (threadfence-reduction pattern). Fixed summation
    // order blk 0..7 -> deterministic regardless of arrival order.
    if (tid == 0) {
        __threadfence();                            // publish g_part writes
        int old = atomicAdd(&g_cnt[b], 1);
        if (old == 7) {
            __threadfence();                        // acquire others' writes
            const float* pp = g_part + (size_t)b * 48;
            float lg[6];
            #pragma unroll
            for (int j = 0; j < 6; j++) lg[j] = fc_b[j];
            #pragma unroll
            for (int blk = 0; blk < 8; blk++)
                #pragma unroll
                for (int j = 0; j < 6; j++) lg[j] += pp[blk * 6 + j];

            float mx = lg[0];
            #pragma unroll
            for (int j = 1; j < 6; j++) mx = fmaxf(mx, lg[j]);
            float e[6], s = 0.0f;
            #pragma unroll
            for (int j = 0; j < 6; j++) { e[j] = expf(lg[j] - mx); s += e[j]; }
            float inv = 1.0f / s;
            #pragma unroll
            for (int j = 0; j < 6; j++) out[b * 6 + j] = e[j] * inv;

            g_cnt[b] = 0;                           // self-reset for replay
        }
    }
}

// ===========================================================================
extern "C" void kernel_launch(void* const* d_in, const int* in_sizes, int n_in,
                              void* d_out, int out_size)
{
    const float* x     = (const float*)d_in[0];
    const float* k1    = (const float*)d_in[1];
    const float* gamma = (const float*)d_in[2];
    const float* beta  = (const float*)d_in[3];
    const float* k2    = (const float*)d_in[4];
    const float* k3    = (const float*)d_in[5];
    const float* fc_w  = (const float*)d_in[6];
    const float* fc_b  = (const float*)d_in[7];
    float* out = (float*)d_out;

    k1_conv_bn_pool<<<dim3(4, 8, BATCH), 192>>>(x, k1, gamma, beta);
    k3a_fold<<<216, 256>>>(k3, fc_w);          // W_eff ready before K2 (stream order)
    k2_conv_pool_dot<<<dim3(2, 4, BATCH), 192>>>(k2, fc_b, out);
}